// round 11
// baseline (speedup 1.0000x reference)
#include <cuda_runtime.h>
#include <cuda_fp16.h>
#include <cstdint>

// SDPA B=4,H=16,S=2048,D=64 fp32. scores = QK^T * 4096 -> one-hot softmax.
// R11: epilogue prefilter. Scattered exact-rescore + V-gather were ~half of
// all L1 work (32 wavefronts per warp LDG). Record approx scores with the
// candidates; epilogue rescans only candidates with approx > amax-0.02
// (typically 1-3) and V-gathers only exact winners (w > 1e-9, ~1-2 rows).
// Main loop identical to R10 (M=32/warp fp16 mma, cp.async ring, reg scan).

#define S_LEN 2048
#define HDIM  64
#define TQ    256
#define THREADS 256
#define TKT   64
#define NKT   (S_LEN / TKT)
#define N_BH  64
#define WINAPPROX 0.12f
#define PREFILTER 0.02f
#define WCUT 0.0051f
#define LSCALE 4096.0f
#define NCAND 32

#define TILE_WORDS 2048
#define NSTAGE 4

#define W_STG 0                                  // 8192 words (epilogue es reuse)
#define W_CS  (W_STG + NSTAGE * TILE_WORDS)      // float cs[256][32]
#define W_CK  (W_CS + TQ * NCAND)                // int   ck[256][32]
#define W_CNT (W_CK + TQ * NCAND)                // int   cnt[256]
#define SMEM_WORDS (W_CNT + TQ)
#define SMEM_BYTES (SMEM_WORDS * 4)              // 99328 B -> 2 CTAs/SM

typedef unsigned long long u64;

__device__ static uint32_t g_kscr[(size_t)N_BH * NKT * TILE_WORDS];

__device__ __forceinline__ void mma_f16(float& d0, float& d1, float& d2, float& d3,
                                        uint32_t a0, uint32_t a1, uint32_t a2, uint32_t a3,
                                        uint32_t b0, uint32_t b1) {
    asm volatile(
        "mma.sync.aligned.m16n8k16.row.col.f32.f16.f16.f32 "
        "{%0,%1,%2,%3}, {%4,%5,%6,%7}, {%8,%9}, {%0,%1,%2,%3};"
        : "+f"(d0), "+f"(d1), "+f"(d2), "+f"(d3)
        : "r"(a0), "r"(a1), "r"(a2), "r"(a3), "r"(b0), "r"(b1));
}
__device__ __forceinline__ uint32_t f16x2(float lo, float hi) {
    uint32_t d;
    asm("cvt.rn.f16x2.f32 %0, %1, %2;" : "=r"(d) : "f"(hi), "f"(lo));
    return d;
}
__device__ __forceinline__ u64 ffma2(u64 a, u64 b, u64 c) {
    u64 d;
    asm("fma.rn.f32x2 %0, %1, %2, %3;" : "=l"(d) : "l"(a), "l"(b), "l"(c));
    return d;
}
__device__ __forceinline__ u64 fadd2(u64 a, u64 b) {
    u64 d;
    asm("add.rn.f32x2 %0, %1, %2;" : "=l"(d) : "l"(a), "l"(b));
    return d;
}
__device__ __forceinline__ float hsum2(u64 a) {
    float x, y;
    asm("mov.b64 {%0, %1}, %2;" : "=f"(x), "=f"(y) : "l"(a));
    return x + y;
}
__device__ __forceinline__ u64 pack2(float x, float y) {
    u64 d;
    asm("mov.b64 %0, {%1, %2};" : "=l"(d) : "f"(x), "f"(y));
    return d;
}
__device__ __forceinline__ void cp16(uint32_t saddr, const void* g) {
    asm volatile("cp.async.cg.shared.global [%0], [%1], 16;" :: "r"(saddr), "l"(g));
}

__global__ void __launch_bounds__(256)
k_convert_kernel(const float* __restrict__ K) {
    const int x = blockIdx.x;
    const int tid = threadIdx.x;
    const int bh = x / NKT, kt = x - bh * NKT;
    const float* kt_base = K + ((long)bh * S_LEN + (long)kt * TKT) * HDIM;
    uint32_t* dst = g_kscr + (size_t)x * TILE_WORDS;
#pragma unroll
    for (int i = 0; i < TILE_WORDS / 256; i++) {
        const int w = i * 256 + tid;
        const int b = w >> 7, iw = w & 127;
        const int nt = b >> 1, p = b & 1;
        const int n = nt * 8 + (iw >> 4);
        const int c = (iw >> 2) & 3, q = iw & 3;
        const int ks = 2 * p + (q >> 1);
        const int d2 = 8 * ks + 4 * (q & 1) + c;
        const float2 v = *(const float2*)(kt_base + n * HDIM + 2 * d2);
        dst[w] = f16x2(v.x, v.y);
    }
}

__global__ void __launch_bounds__(THREADS, 2)
sdpa_r11_kernel(const float* __restrict__ Q,
                const float* __restrict__ K,
                const float* __restrict__ V,
                float* __restrict__ O) {
    extern __shared__ float sm[];
    float* csq = sm + W_CS;
    int* ckq  = (int*)(sm + W_CK);
    int* cntq = (int*)(sm + W_CNT);
    uint32_t sb;
    asm("{ .reg .u64 t; cvta.to.shared.u64 t, %1; cvt.u32.u64 %0, t; }" : "=r"(sb) : "l"(sm));

    const int tid  = threadIdx.x;
    const int lane = tid & 31;
    const int warp = tid >> 5;
    const int g    = lane >> 2;
    const int t    = lane & 3;
    const int bh   = blockIdx.y;
    const long bhoff = (long)bh * S_LEN * HDIM;
    const float* kb = K + bhoff;
    const float* vb = V + bhoff;
    const uint32_t* gsrc = g_kscr + (size_t)bh * NKT * TILE_WORDS;

    cntq[tid] = 0;

#pragma unroll
    for (int s = 0; s < NSTAGE - 1; s++) {
        const uint32_t sa = sb + (W_STG + s * TILE_WORDS) * 4 + tid * 32;
        const uint32_t* gp = gsrc + s * TILE_WORDS + tid * 8;
        cp16(sa, gp);
        cp16(sa + 16, gp + 4);
        asm volatile("cp.async.commit_group;" ::: "memory");
    }

    uint32_t af[4][8];
    {
        const float* r0 = Q + ((long)bh * S_LEN + blockIdx.x * TQ + warp * 32 + g) * HDIM;
#pragma unroll
        for (int s = 0; s < 4; s++) {
            const int c = 16 * s + 2 * t;
            float2 v;
            v = *(const float2*)(r0 + c);                 af[s][0] = f16x2(v.x, v.y);
            v = *(const float2*)(r0 + 8 * HDIM + c);      af[s][1] = f16x2(v.x, v.y);
            v = *(const float2*)(r0 + c + 8);             af[s][2] = f16x2(v.x, v.y);
            v = *(const float2*)(r0 + 8 * HDIM + c + 8);  af[s][3] = f16x2(v.x, v.y);
            v = *(const float2*)(r0 + 16 * HDIM + c);     af[s][4] = f16x2(v.x, v.y);
            v = *(const float2*)(r0 + 24 * HDIM + c);     af[s][5] = f16x2(v.x, v.y);
            v = *(const float2*)(r0 + 16 * HDIM + c + 8); af[s][6] = f16x2(v.x, v.y);
            v = *(const float2*)(r0 + 24 * HDIM + c + 8); af[s][7] = f16x2(v.x, v.y);
        }
    }

    float mq[4]  = {-INFINITY, -INFINITY, -INFINITY, -INFINITY};
    float thq[4] = {-INFINITY, -INFINITY, -INFINITY, -INFINITY};

    for (int kt = 0; kt < NKT; kt++) {
        asm volatile("cp.async.wait_group 2;" ::: "memory");
        __syncthreads();

        if (kt + 3 < NKT) {
            const int s = (kt + 3) & (NSTAGE - 1);
            const uint32_t sa = sb + (W_STG + s * TILE_WORDS) * 4 + tid * 32;
            const uint32_t* gp = gsrc + (kt + 3) * TILE_WORDS + tid * 8;
            cp16(sa, gp);
            cp16(sa + 16, gp + 4);
        }
        asm volatile("cp.async.commit_group;" ::: "memory");

        const uint32_t* sKB = (const uint32_t*)sm + W_STG + (kt & (NSTAGE - 1)) * TILE_WORDS;

        float acc[8][8];
#pragma unroll
        for (int nt = 0; nt < 8; nt++)
#pragma unroll
            for (int e = 0; e < 8; e++) acc[nt][e] = 0.0f;

#pragma unroll
        for (int p = 0; p < 2; p++) {
#pragma unroll
            for (int ng = 0; ng < 2; ng++) {
                uint4 bf[4];
#pragma unroll
                for (int i = 0; i < 4; i++)
                    bf[i] = *(const uint4*)(sKB + (((ng * 4 + i) * 2 + p) << 7) + lane * 4);
#pragma unroll
                for (int i = 0; i < 4; i++) {
                    const int nt = ng * 4 + i;
                    mma_f16(acc[nt][0], acc[nt][1], acc[nt][2], acc[nt][3],
                            af[2 * p][0], af[2 * p][1], af[2 * p][2], af[2 * p][3],
                            bf[i].x, bf[i].y);
                    mma_f16(acc[nt][4], acc[nt][5], acc[nt][6], acc[nt][7],
                            af[2 * p][4], af[2 * p][5], af[2 * p][6], af[2 * p][7],
                            bf[i].x, bf[i].y);
                }
#pragma unroll
                for (int i = 0; i < 4; i++) {
                    const int nt = ng * 4 + i;
                    mma_f16(acc[nt][0], acc[nt][1], acc[nt][2], acc[nt][3],
                            af[2 * p + 1][0], af[2 * p + 1][1],
                            af[2 * p + 1][2], af[2 * p + 1][3],
                            bf[i].z, bf[i].w);
                    mma_f16(acc[nt][4], acc[nt][5], acc[nt][6], acc[nt][7],
                            af[2 * p + 1][4], af[2 * p + 1][5],
                            af[2 * p + 1][6], af[2 * p + 1][7],
                            bf[i].z, bf[i].w);
                }
            }
        }

        const int kbase = kt * TKT;
#pragma unroll
        for (int qi = 0; qi < 4; qi++) {
            float mx = fmaxf(acc[0][2 * qi], acc[0][2 * qi + 1]);
#pragma unroll
            for (int nt = 1; nt < 8; nt++)
                mx = fmaxf(mx, fmaxf(acc[nt][2 * qi], acc[nt][2 * qi + 1]));
            mx = fmaxf(mx, __shfl_xor_sync(0xFFFFFFFFu, mx, 1));
            mx = fmaxf(mx, __shfl_xor_sync(0xFFFFFFFFu, mx, 2));

            if (mx > thq[qi]) {   // rare
                mq[qi] = fmaxf(mq[qi], mx);
                thq[qi] = mq[qi] - WINAPPROX;
                const int q = warp * 32 + g + 8 * qi;
#pragma unroll
                for (int nt = 0; nt < 8; nt++) {
#pragma unroll
                    for (int e = 0; e < 2; e++) {
                        const float s = acc[nt][2 * qi + e];
                        if (s > thq[qi]) {
                            const int slot = atomicAdd(&cntq[q], 1);
                            if (slot < NCAND) {
                                csq[q * NCAND + slot] = s;
                                ckq[q * NCAND + slot] = kbase + nt * 8 + 2 * t + e;
                            }
                        }
                    }
                }
            }
        }
    }

    asm volatile("cp.async.wait_group 0;" ::: "memory");
    __syncthreads();

    // ---- epilogue: prefiltered exact rescore + sparse V gather ----
    {
        float* es = sm + W_STG;   // [i*TQ + tid]

        const long qrow = (long)bh * S_LEN + blockIdx.x * TQ + tid;
        const u64* qg = (const u64*)(Q + qrow * HDIM);
        u64 q2[HDIM / 2];
#pragma unroll
        for (int j = 0; j < HDIM / 2; j++) q2[j] = qg[j];

        int nc = cntq[tid];
        if (nc > NCAND) nc = NCAND;

        // pass 1: approx max over candidates
        float amax = -INFINITY;
        for (int i = 0; i < nc; i++) amax = fmaxf(amax, csq[tid * NCAND + i]);
        const float pfthr = amax - PREFILTER;

        // pass 2: exact rescore of survivors only (typically 1-3)
        float em = -INFINITY;
        for (int i = 0; i < nc; i++) {
            float e = -INFINITY;
            if (csq[tid * NCAND + i] > pfthr) {
                const u64* kr = (const u64*)(kb + (long)ckq[tid * NCAND + i] * HDIM);
                u64 a0 = 0ULL, a1 = 0ULL, a2 = 0ULL, a3 = 0ULL;
#pragma unroll
                for (int j = 0; j < 8; j++) {
                    a0 = ffma2(q2[4 * j + 0], kr[4 * j + 0], a0);
                    a1 = ffma2(q2[4 * j + 1], kr[4 * j + 1], a1);
                    a2 = ffma2(q2[4 * j + 2], kr[4 * j + 2], a2);
                    a3 = ffma2(q2[4 * j + 3], kr[4 * j + 3], a3);
                }
                e = hsum2(fadd2(fadd2(a0, a1), fadd2(a2, a3)));
                em = fmaxf(em, e);
            }
            es[i * TQ + tid] = e;
        }

        // pass 3: weights + V gather for exact winners only (typically 1-2)
        u64 o2[HDIM / 2];
#pragma unroll
        for (int j = 0; j < HDIM / 2; j++) o2[j] = 0ULL;
        float lsum = 0.0f;
        const float wthr = em - WCUT;
        for (int i = 0; i < nc; i++) {
            const float e = es[i * TQ + tid];
            if (e > wthr) {
                const float w = __expf(LSCALE * (e - em));
                lsum += w;
                const u64* v2 = (const u64*)(vb + (long)ckq[tid * NCAND + i] * HDIM);
                const u64 w2 = pack2(w, w);
#pragma unroll
                for (int j = 0; j < HDIM / 2; j++) o2[j] = ffma2(w2, v2[j], o2[j]);
            }
        }
        const float inv = 1.0f / lsum;
        const u64 inv2 = pack2(inv, inv);
        u64* og = (u64*)(O + qrow * HDIM);
#pragma unroll
        for (int j = 0; j < HDIM / 2; j++) {
            u64 r;
            asm("mul.rn.f32x2 %0, %1, %2;" : "=l"(r) : "l"(o2[j]), "l"(inv2));
            og[j] = r;
        }
    }
}

extern "C" void kernel_launch(void* const* d_in, const int* in_sizes, int n_in,
                              void* d_out, int out_size) {
    const float* Q = (const float*)d_in[0];
    const float* K = (const float*)d_in[1];
    const float* V = (const float*)d_in[2];
    float* O = (float*)d_out;

    k_convert_kernel<<<N_BH * NKT, 256>>>(K);

    cudaFuncSetAttribute(sdpa_r11_kernel,
                         cudaFuncAttributeMaxDynamicSharedMemorySize, SMEM_BYTES);
    dim3 grid(S_LEN / TQ, N_BH);  // (8, 64)
    dim3 block(THREADS);
    sdpa_r11_kernel<<<grid, block, SMEM_BYTES>>>(Q, K, V, O);
}

// round 12
// speedup vs baseline: 1.5031x; 1.5031x over previous
#include <cuda_runtime.h>
#include <cuda_fp16.h>
#include <cstdint>

// SDPA B=4,H=16,S=2048,D=64 fp32. scores = QK^T * 4096 -> one-hot softmax.
// R12: R10 main loop (proven 290us) + smem-NEUTRAL epilogue prefilter.
// Candidate = ONE packed u32: high 21 bits = approx-score f32 bits, low 11
// bits = key (score truncation err <= 2^-7, margin-covered). Epilogue:
// amax over packed scores -> exact fp32 rescore only survivors (~1-3) ->
// V-gather only exact winners (~1-2). R11's +32KB smem (which cost the L1D
// carveout and regressed) is avoided entirely.

#define S_LEN 2048
#define HDIM  64
#define TQ    256
#define THREADS 256
#define TKT   64
#define NKT   (S_LEN / TKT)
#define N_BH  64
#define WINAPPROX 0.12f
#define PREFILTER 0.05f
#define WCUT 0.0051f
#define LSCALE 4096.0f
#define NCAND 32
#define KEYMASK 0x7FFu
#define SCOREMASK 0xFFFFF800u

#define TILE_WORDS 2048
#define NSTAGE 4

#define W_STG 0                                  // 8192 words (epilogue es reuse)
#define W_CK  (W_STG + NSTAGE * TILE_WORDS)      // u32 packed cand [256][32]
#define W_CNT (W_CK + TQ * NCAND)                // int cnt[256]
#define SMEM_WORDS (W_CNT + TQ)
#define SMEM_BYTES (SMEM_WORDS * 4)              // ~66.6 KB -> 2 CTAs/SM

typedef unsigned long long u64;

__device__ static uint32_t g_kscr[(size_t)N_BH * NKT * TILE_WORDS];

__device__ __forceinline__ void mma_f16(float& d0, float& d1, float& d2, float& d3,
                                        uint32_t a0, uint32_t a1, uint32_t a2, uint32_t a3,
                                        uint32_t b0, uint32_t b1) {
    asm volatile(
        "mma.sync.aligned.m16n8k16.row.col.f32.f16.f16.f32 "
        "{%0,%1,%2,%3}, {%4,%5,%6,%7}, {%8,%9}, {%0,%1,%2,%3};"
        : "+f"(d0), "+f"(d1), "+f"(d2), "+f"(d3)
        : "r"(a0), "r"(a1), "r"(a2), "r"(a3), "r"(b0), "r"(b1));
}
__device__ __forceinline__ uint32_t f16x2(float lo, float hi) {
    uint32_t d;
    asm("cvt.rn.f16x2.f32 %0, %1, %2;" : "=r"(d) : "f"(hi), "f"(lo));
    return d;
}
__device__ __forceinline__ u64 ffma2(u64 a, u64 b, u64 c) {
    u64 d;
    asm("fma.rn.f32x2 %0, %1, %2, %3;" : "=l"(d) : "l"(a), "l"(b), "l"(c));
    return d;
}
__device__ __forceinline__ u64 fadd2(u64 a, u64 b) {
    u64 d;
    asm("add.rn.f32x2 %0, %1, %2;" : "=l"(d) : "l"(a), "l"(b));
    return d;
}
__device__ __forceinline__ float hsum2(u64 a) {
    float x, y;
    asm("mov.b64 {%0, %1}, %2;" : "=f"(x), "=f"(y) : "l"(a));
    return x + y;
}
__device__ __forceinline__ u64 pack2(float x, float y) {
    u64 d;
    asm("mov.b64 %0, {%1, %2};" : "=l"(d) : "f"(x), "f"(y));
    return d;
}
__device__ __forceinline__ void cp16(uint32_t saddr, const void* g) {
    asm volatile("cp.async.cg.shared.global [%0], [%1], 16;" :: "r"(saddr), "l"(g));
}

__global__ void __launch_bounds__(256)
k_convert_kernel(const float* __restrict__ K) {
    const int x = blockIdx.x;
    const int tid = threadIdx.x;
    const int bh = x / NKT, kt = x - bh * NKT;
    const float* kt_base = K + ((long)bh * S_LEN + (long)kt * TKT) * HDIM;
    uint32_t* dst = g_kscr + (size_t)x * TILE_WORDS;
#pragma unroll
    for (int i = 0; i < TILE_WORDS / 256; i++) {
        const int w = i * 256 + tid;
        const int b = w >> 7, iw = w & 127;
        const int nt = b >> 1, p = b & 1;
        const int n = nt * 8 + (iw >> 4);
        const int c = (iw >> 2) & 3, q = iw & 3;
        const int ks = 2 * p + (q >> 1);
        const int d2 = 8 * ks + 4 * (q & 1) + c;
        const float2 v = *(const float2*)(kt_base + n * HDIM + 2 * d2);
        dst[w] = f16x2(v.x, v.y);
    }
}

__global__ void __launch_bounds__(THREADS, 2)
sdpa_r12_kernel(const float* __restrict__ Q,
                const float* __restrict__ K,
                const float* __restrict__ V,
                float* __restrict__ O) {
    extern __shared__ float sm[];
    uint32_t* ckq = (uint32_t*)(sm + W_CK);
    int* cntq = (int*)(sm + W_CNT);
    uint32_t sb;
    asm("{ .reg .u64 t; cvta.to.shared.u64 t, %1; cvt.u32.u64 %0, t; }" : "=r"(sb) : "l"(sm));

    const int tid  = threadIdx.x;
    const int lane = tid & 31;
    const int warp = tid >> 5;
    const int g    = lane >> 2;
    const int t    = lane & 3;
    const int bh   = blockIdx.y;
    const long bhoff = (long)bh * S_LEN * HDIM;
    const float* kb = K + bhoff;
    const float* vb = V + bhoff;
    const uint32_t* gsrc = g_kscr + (size_t)bh * NKT * TILE_WORDS;

    cntq[tid] = 0;

#pragma unroll
    for (int s = 0; s < NSTAGE - 1; s++) {
        const uint32_t sa = sb + (W_STG + s * TILE_WORDS) * 4 + tid * 32;
        const uint32_t* gp = gsrc + s * TILE_WORDS + tid * 8;
        cp16(sa, gp);
        cp16(sa + 16, gp + 4);
        asm volatile("cp.async.commit_group;" ::: "memory");
    }

    uint32_t af[4][8];
    {
        const float* r0 = Q + ((long)bh * S_LEN + blockIdx.x * TQ + warp * 32 + g) * HDIM;
#pragma unroll
        for (int s = 0; s < 4; s++) {
            const int c = 16 * s + 2 * t;
            float2 v;
            v = *(const float2*)(r0 + c);                 af[s][0] = f16x2(v.x, v.y);
            v = *(const float2*)(r0 + 8 * HDIM + c);      af[s][1] = f16x2(v.x, v.y);
            v = *(const float2*)(r0 + c + 8);             af[s][2] = f16x2(v.x, v.y);
            v = *(const float2*)(r0 + 8 * HDIM + c + 8);  af[s][3] = f16x2(v.x, v.y);
            v = *(const float2*)(r0 + 16 * HDIM + c);     af[s][4] = f16x2(v.x, v.y);
            v = *(const float2*)(r0 + 24 * HDIM + c);     af[s][5] = f16x2(v.x, v.y);
            v = *(const float2*)(r0 + 16 * HDIM + c + 8); af[s][6] = f16x2(v.x, v.y);
            v = *(const float2*)(r0 + 24 * HDIM + c + 8); af[s][7] = f16x2(v.x, v.y);
        }
    }

    float mq[4]  = {-INFINITY, -INFINITY, -INFINITY, -INFINITY};
    float thq[4] = {-INFINITY, -INFINITY, -INFINITY, -INFINITY};

    for (int kt = 0; kt < NKT; kt++) {
        asm volatile("cp.async.wait_group 2;" ::: "memory");
        __syncthreads();

        if (kt + 3 < NKT) {
            const int s = (kt + 3) & (NSTAGE - 1);
            const uint32_t sa = sb + (W_STG + s * TILE_WORDS) * 4 + tid * 32;
            const uint32_t* gp = gsrc + (kt + 3) * TILE_WORDS + tid * 8;
            cp16(sa, gp);
            cp16(sa + 16, gp + 4);
        }
        asm volatile("cp.async.commit_group;" ::: "memory");

        const uint32_t* sKB = (const uint32_t*)sm + W_STG + (kt & (NSTAGE - 1)) * TILE_WORDS;

        float acc[8][8];
#pragma unroll
        for (int nt = 0; nt < 8; nt++)
#pragma unroll
            for (int e = 0; e < 8; e++) acc[nt][e] = 0.0f;

#pragma unroll
        for (int p = 0; p < 2; p++) {
#pragma unroll
            for (int ng = 0; ng < 2; ng++) {
                uint4 bf[4];
#pragma unroll
                for (int i = 0; i < 4; i++)
                    bf[i] = *(const uint4*)(sKB + (((ng * 4 + i) * 2 + p) << 7) + lane * 4);
#pragma unroll
                for (int i = 0; i < 4; i++) {
                    const int nt = ng * 4 + i;
                    mma_f16(acc[nt][0], acc[nt][1], acc[nt][2], acc[nt][3],
                            af[2 * p][0], af[2 * p][1], af[2 * p][2], af[2 * p][3],
                            bf[i].x, bf[i].y);
                    mma_f16(acc[nt][4], acc[nt][5], acc[nt][6], acc[nt][7],
                            af[2 * p][4], af[2 * p][5], af[2 * p][6], af[2 * p][7],
                            bf[i].x, bf[i].y);
                }
#pragma unroll
                for (int i = 0; i < 4; i++) {
                    const int nt = ng * 4 + i;
                    mma_f16(acc[nt][0], acc[nt][1], acc[nt][2], acc[nt][3],
                            af[2 * p + 1][0], af[2 * p + 1][1],
                            af[2 * p + 1][2], af[2 * p + 1][3],
                            bf[i].z, bf[i].w);
                    mma_f16(acc[nt][4], acc[nt][5], acc[nt][6], acc[nt][7],
                            af[2 * p + 1][4], af[2 * p + 1][5],
                            af[2 * p + 1][6], af[2 * p + 1][7],
                            bf[i].z, bf[i].w);
                }
            }
        }

        const int kbase = kt * TKT;
#pragma unroll
        for (int qi = 0; qi < 4; qi++) {
            float mx = fmaxf(acc[0][2 * qi], acc[0][2 * qi + 1]);
#pragma unroll
            for (int nt = 1; nt < 8; nt++)
                mx = fmaxf(mx, fmaxf(acc[nt][2 * qi], acc[nt][2 * qi + 1]));
            mx = fmaxf(mx, __shfl_xor_sync(0xFFFFFFFFu, mx, 1));
            mx = fmaxf(mx, __shfl_xor_sync(0xFFFFFFFFu, mx, 2));

            if (mx > thq[qi]) {   // rare
                mq[qi] = fmaxf(mq[qi], mx);
                thq[qi] = mq[qi] - WINAPPROX;
                const int q = warp * 32 + g + 8 * qi;
#pragma unroll
                for (int nt = 0; nt < 8; nt++) {
#pragma unroll
                    for (int e = 0; e < 2; e++) {
                        const float s = acc[nt][2 * qi + e];
                        if (s > thq[qi]) {
                            const int slot = atomicAdd(&cntq[q], 1);
                            if (slot < NCAND) {
                                const uint32_t key = (uint32_t)(kbase + nt * 8 + 2 * t + e);
                                ckq[q * NCAND + slot] =
                                    (__float_as_uint(s) & SCOREMASK) | key;
                            }
                        }
                    }
                }
            }
        }
    }

    asm volatile("cp.async.wait_group 0;" ::: "memory");
    __syncthreads();

    // ---- epilogue: packed-prefiltered exact rescore + sparse V gather ----
    {
        float* es = sm + W_STG;   // [i*TQ + tid]

        const long qrow = (long)bh * S_LEN + blockIdx.x * TQ + tid;
        const u64* qg = (const u64*)(Q + qrow * HDIM);
        u64 q2[HDIM / 2];
#pragma unroll
        for (int j = 0; j < HDIM / 2; j++) q2[j] = qg[j];

        int nc = cntq[tid];
        if (nc > NCAND) nc = NCAND;

        // pass 1: approx max over packed candidate scores
        float amax = -INFINITY;
        for (int i = 0; i < nc; i++)
            amax = fmaxf(amax, __uint_as_float(ckq[tid * NCAND + i] & SCOREMASK));
        const float pfthr = amax - PREFILTER;

        // pass 2: exact rescore of survivors only (typically 1-3)
        float em = -INFINITY;
        for (int i = 0; i < nc; i++) {
            const uint32_t cw = ckq[tid * NCAND + i];
            float e = -INFINITY;
            if (__uint_as_float(cw & SCOREMASK) > pfthr) {
                const u64* kr = (const u64*)(kb + (long)(cw & KEYMASK) * HDIM);
                u64 a0 = 0ULL, a1 = 0ULL, a2 = 0ULL, a3 = 0ULL;
#pragma unroll
                for (int j = 0; j < 8; j++) {
                    a0 = ffma2(q2[4 * j + 0], kr[4 * j + 0], a0);
                    a1 = ffma2(q2[4 * j + 1], kr[4 * j + 1], a1);
                    a2 = ffma2(q2[4 * j + 2], kr[4 * j + 2], a2);
                    a3 = ffma2(q2[4 * j + 3], kr[4 * j + 3], a3);
                }
                e = hsum2(fadd2(fadd2(a0, a1), fadd2(a2, a3)));
                em = fmaxf(em, e);
            }
            es[i * TQ + tid] = e;
        }

        // pass 3: weights + V gather for exact winners only (typically 1-2)
        u64 o2[HDIM / 2];
#pragma unroll
        for (int j = 0; j < HDIM / 2; j++) o2[j] = 0ULL;
        float lsum = 0.0f;
        const float wthr = em - WCUT;
        for (int i = 0; i < nc; i++) {
            const float e = es[i * TQ + tid];
            if (e > wthr) {
                const float w = __expf(LSCALE * (e - em));
                lsum += w;
                const u64* v2 =
                    (const u64*)(vb + (long)(ckq[tid * NCAND + i] & KEYMASK) * HDIM);
                const u64 w2 = pack2(w, w);
#pragma unroll
                for (int j = 0; j < HDIM / 2; j++) o2[j] = ffma2(w2, v2[j], o2[j]);
            }
        }
        const float inv = 1.0f / lsum;
        const u64 inv2 = pack2(inv, inv);
        u64* og = (u64*)(O + qrow * HDIM);
#pragma unroll
        for (int j = 0; j < HDIM / 2; j++) {
            u64 r;
            asm("mul.rn.f32x2 %0, %1, %2;" : "=l"(r) : "l"(o2[j]), "l"(inv2));
            og[j] = r;
        }
    }
}

extern "C" void kernel_launch(void* const* d_in, const int* in_sizes, int n_in,
                              void* d_out, int out_size) {
    const float* Q = (const float*)d_in[0];
    const float* K = (const float*)d_in[1];
    const float* V = (const float*)d_in[2];
    float* O = (float*)d_out;

    k_convert_kernel<<<N_BH * NKT, 256>>>(K);

    cudaFuncSetAttribute(sdpa_r12_kernel,
                         cudaFuncAttributeMaxDynamicSharedMemorySize, SMEM_BYTES);
    dim3 grid(S_LEN / TQ, N_BH);  // (8, 64)
    dim3 block(THREADS);
    sdpa_r12_kernel<<<grid, block, SMEM_BYTES>>>(Q, K, V, O);
}

// round 13
// speedup vs baseline: 1.6893x; 1.1238x over previous
#include <cuda_runtime.h>
#include <cuda_fp16.h>
#include <cstdint>

// SDPA B=4,H=16,S=2048,D=64 fp32. scores = QK^T * 4096 -> one-hot softmax.
// R13: barrier-free main loop. K fragments are read DIRECTLY from the
// pre-converted global scratch (LDG.128, lane-contiguous; L2-resident,
// L1-reused across the CTA's warps) -- no smem staging, no cp.async, and
// zero per-tile __syncthreads: warps run all 32 tiles fully decoupled.
// Packed-candidate prefilter epilogue unchanged from R12 (244us).

#define S_LEN 2048
#define HDIM  64
#define TQ    256
#define THREADS 256
#define TKT   64
#define NKT   (S_LEN / TKT)
#define N_BH  64
#define WINAPPROX 0.12f
#define PREFILTER 0.05f
#define WCUT 0.0051f
#define LSCALE 4096.0f
#define NCAND 32
#define KEYMASK 0x7FFu
#define SCOREMASK 0xFFFFF800u

#define TILE_WORDS 2048

#define W_CK  0                                  // u32 packed cand [256][32]
#define W_ES  (W_CK + TQ * NCAND)                // float es[32][256]
#define W_CNT (W_ES + TQ * NCAND)                // int cnt[256]
#define SMEM_WORDS (W_CNT + TQ)
#define SMEM_BYTES (SMEM_WORDS * 4)              // ~66.6 KB -> 2 CTAs/SM

typedef unsigned long long u64;

__device__ static uint32_t g_kscr[(size_t)N_BH * NKT * TILE_WORDS];

__device__ __forceinline__ void mma_f16(float& d0, float& d1, float& d2, float& d3,
                                        uint32_t a0, uint32_t a1, uint32_t a2, uint32_t a3,
                                        uint32_t b0, uint32_t b1) {
    asm volatile(
        "mma.sync.aligned.m16n8k16.row.col.f32.f16.f16.f32 "
        "{%0,%1,%2,%3}, {%4,%5,%6,%7}, {%8,%9}, {%0,%1,%2,%3};"
        : "+f"(d0), "+f"(d1), "+f"(d2), "+f"(d3)
        : "r"(a0), "r"(a1), "r"(a2), "r"(a3), "r"(b0), "r"(b1));
}
__device__ __forceinline__ uint32_t f16x2(float lo, float hi) {
    uint32_t d;
    asm("cvt.rn.f16x2.f32 %0, %1, %2;" : "=r"(d) : "f"(hi), "f"(lo));
    return d;
}
__device__ __forceinline__ u64 ffma2(u64 a, u64 b, u64 c) {
    u64 d;
    asm("fma.rn.f32x2 %0, %1, %2, %3;" : "=l"(d) : "l"(a), "l"(b), "l"(c));
    return d;
}
__device__ __forceinline__ u64 fadd2(u64 a, u64 b) {
    u64 d;
    asm("add.rn.f32x2 %0, %1, %2;" : "=l"(d) : "l"(a), "l"(b));
    return d;
}
__device__ __forceinline__ float hsum2(u64 a) {
    float x, y;
    asm("mov.b64 {%0, %1}, %2;" : "=f"(x), "=f"(y) : "l"(a));
    return x + y;
}
__device__ __forceinline__ u64 pack2(float x, float y) {
    u64 d;
    asm("mov.b64 %0, {%1, %2};" : "=l"(d) : "f"(x), "f"(y));
    return d;
}

__global__ void __launch_bounds__(256)
k_convert_kernel(const float* __restrict__ K) {
    const int x = blockIdx.x;
    const int tid = threadIdx.x;
    const int bh = x / NKT, kt = x - bh * NKT;
    const float* kt_base = K + ((long)bh * S_LEN + (long)kt * TKT) * HDIM;
    uint32_t* dst = g_kscr + (size_t)x * TILE_WORDS;
#pragma unroll
    for (int i = 0; i < TILE_WORDS / 256; i++) {
        const int w = i * 256 + tid;
        const int b = w >> 7, iw = w & 127;
        const int nt = b >> 1, p = b & 1;
        const int n = nt * 8 + (iw >> 4);
        const int c = (iw >> 2) & 3, q = iw & 3;
        const int ks = 2 * p + (q >> 1);
        const int d2 = 8 * ks + 4 * (q & 1) + c;
        const float2 v = *(const float2*)(kt_base + n * HDIM + 2 * d2);
        dst[w] = f16x2(v.x, v.y);
    }
}

__global__ void __launch_bounds__(THREADS, 2)
sdpa_r13_kernel(const float* __restrict__ Q,
                const float* __restrict__ K,
                const float* __restrict__ V,
                float* __restrict__ O) {
    extern __shared__ float sm[];
    uint32_t* ckq = (uint32_t*)(sm + W_CK);
    int* cntq = (int*)(sm + W_CNT);

    const int tid  = threadIdx.x;
    const int lane = tid & 31;
    const int warp = tid >> 5;
    const int g    = lane >> 2;
    const int t    = lane & 3;
    const int bh   = blockIdx.y;
    const long bhoff = (long)bh * S_LEN * HDIM;
    const float* kb = K + bhoff;
    const float* vb = V + bhoff;
    // warp's fragment base: tile words start at bh*NKT*TILE_WORDS; each warp
    // reads blocks b=0..15 at word offset b*128 + lane*4 (uint4 per lane).
    const uint4* gfrag = (const uint4*)(g_kscr + (size_t)bh * NKT * TILE_WORDS) + lane;

    cntq[tid] = 0;

    // ---- A fragments: warp's 32 query rows ----
    uint32_t af[4][8];
    {
        const float* r0 = Q + ((long)bh * S_LEN + blockIdx.x * TQ + warp * 32 + g) * HDIM;
#pragma unroll
        for (int s = 0; s < 4; s++) {
            const int c = 16 * s + 2 * t;
            float2 v;
            v = *(const float2*)(r0 + c);                 af[s][0] = f16x2(v.x, v.y);
            v = *(const float2*)(r0 + 8 * HDIM + c);      af[s][1] = f16x2(v.x, v.y);
            v = *(const float2*)(r0 + c + 8);             af[s][2] = f16x2(v.x, v.y);
            v = *(const float2*)(r0 + 8 * HDIM + c + 8);  af[s][3] = f16x2(v.x, v.y);
            v = *(const float2*)(r0 + 16 * HDIM + c);     af[s][4] = f16x2(v.x, v.y);
            v = *(const float2*)(r0 + 24 * HDIM + c);     af[s][5] = f16x2(v.x, v.y);
            v = *(const float2*)(r0 + 16 * HDIM + c + 8); af[s][6] = f16x2(v.x, v.y);
            v = *(const float2*)(r0 + 24 * HDIM + c + 8); af[s][7] = f16x2(v.x, v.y);
        }
    }

    float mq[4]  = {-INFINITY, -INFINITY, -INFINITY, -INFINITY};
    float thq[4] = {-INFINITY, -INFINITY, -INFINITY, -INFINITY};

    // ---- barrier-free main loop: each warp streams all 32 tiles ----
#pragma unroll 1
    for (int kt = 0; kt < NKT; kt++) {
        const uint4* tf = gfrag + (size_t)kt * (TILE_WORDS / 4);

        float acc[8][8];
#pragma unroll
        for (int nt = 0; nt < 8; nt++)
#pragma unroll
            for (int e = 0; e < 8; e++) acc[nt][e] = 0.0f;

#pragma unroll
        for (int p = 0; p < 2; p++) {
#pragma unroll
            for (int ng = 0; ng < 2; ng++) {
                uint4 bf[4];
#pragma unroll
                for (int i = 0; i < 4; i++)
                    bf[i] = __ldg(tf + (((ng * 4 + i) * 2 + p) << 5));
#pragma unroll
                for (int i = 0; i < 4; i++) {
                    const int nt = ng * 4 + i;
                    mma_f16(acc[nt][0], acc[nt][1], acc[nt][2], acc[nt][3],
                            af[2 * p][0], af[2 * p][1], af[2 * p][2], af[2 * p][3],
                            bf[i].x, bf[i].y);
                    mma_f16(acc[nt][4], acc[nt][5], acc[nt][6], acc[nt][7],
                            af[2 * p][4], af[2 * p][5], af[2 * p][6], af[2 * p][7],
                            bf[i].x, bf[i].y);
                }
#pragma unroll
                for (int i = 0; i < 4; i++) {
                    const int nt = ng * 4 + i;
                    mma_f16(acc[nt][0], acc[nt][1], acc[nt][2], acc[nt][3],
                            af[2 * p + 1][0], af[2 * p + 1][1],
                            af[2 * p + 1][2], af[2 * p + 1][3],
                            bf[i].z, bf[i].w);
                    mma_f16(acc[nt][4], acc[nt][5], acc[nt][6], acc[nt][7],
                            af[2 * p + 1][4], af[2 * p + 1][5],
                            af[2 * p + 1][6], af[2 * p + 1][7],
                            bf[i].z, bf[i].w);
                }
            }
        }

        const int kbase = kt * TKT;
#pragma unroll
        for (int qi = 0; qi < 4; qi++) {
            float mx = fmaxf(acc[0][2 * qi], acc[0][2 * qi + 1]);
#pragma unroll
            for (int nt = 1; nt < 8; nt++)
                mx = fmaxf(mx, fmaxf(acc[nt][2 * qi], acc[nt][2 * qi + 1]));
            mx = fmaxf(mx, __shfl_xor_sync(0xFFFFFFFFu, mx, 1));
            mx = fmaxf(mx, __shfl_xor_sync(0xFFFFFFFFu, mx, 2));

            if (mx > thq[qi]) {   // rare
                mq[qi] = fmaxf(mq[qi], mx);
                thq[qi] = mq[qi] - WINAPPROX;
                const int q = warp * 32 + g + 8 * qi;
#pragma unroll
                for (int nt = 0; nt < 8; nt++) {
#pragma unroll
                    for (int e = 0; e < 2; e++) {
                        const float s = acc[nt][2 * qi + e];
                        if (s > thq[qi]) {
                            const int slot = atomicAdd(&cntq[q], 1);
                            if (slot < NCAND) {
                                const uint32_t key = (uint32_t)(kbase + nt * 8 + 2 * t + e);
                                ckq[q * NCAND + slot] =
                                    (__float_as_uint(s) & SCOREMASK) | key;
                            }
                        }
                    }
                }
            }
        }
    }

    __syncthreads();   // all warps' candidate pushes visible

    // ---- epilogue: packed-prefiltered exact rescore + sparse V gather ----
    {
        float* es = sm + W_ES;   // [i*TQ + tid]

        const long qrow = (long)bh * S_LEN + blockIdx.x * TQ + tid;
        const u64* qg = (const u64*)(Q + qrow * HDIM);
        u64 q2[HDIM / 2];
#pragma unroll
        for (int j = 0; j < HDIM / 2; j++) q2[j] = qg[j];

        int nc = cntq[tid];
        if (nc > NCAND) nc = NCAND;

        // pass 1: approx max over packed candidate scores
        float amax = -INFINITY;
        for (int i = 0; i < nc; i++)
            amax = fmaxf(amax, __uint_as_float(ckq[tid * NCAND + i] & SCOREMASK));
        const float pfthr = amax - PREFILTER;

        // pass 2: exact rescore of survivors only (typically 1-3)
        float em = -INFINITY;
        for (int i = 0; i < nc; i++) {
            const uint32_t cw = ckq[tid * NCAND + i];
            float e = -INFINITY;
            if (__uint_as_float(cw & SCOREMASK) > pfthr) {
                const u64* kr = (const u64*)(kb + (long)(cw & KEYMASK) * HDIM);
                u64 a0 = 0ULL, a1 = 0ULL, a2 = 0ULL, a3 = 0ULL;
#pragma unroll
                for (int j = 0; j < 8; j++) {
                    a0 = ffma2(q2[4 * j + 0], kr[4 * j + 0], a0);
                    a1 = ffma2(q2[4 * j + 1], kr[4 * j + 1], a1);
                    a2 = ffma2(q2[4 * j + 2], kr[4 * j + 2], a2);
                    a3 = ffma2(q2[4 * j + 3], kr[4 * j + 3], a3);
                }
                e = hsum2(fadd2(fadd2(a0, a1), fadd2(a2, a3)));
                em = fmaxf(em, e);
            }
            es[i * TQ + tid] = e;
        }

        // pass 3: weights + V gather for exact winners only (typically 1-2)
        u64 o2[HDIM / 2];
#pragma unroll
        for (int j = 0; j < HDIM / 2; j++) o2[j] = 0ULL;
        float lsum = 0.0f;
        const float wthr = em - WCUT;
        for (int i = 0; i < nc; i++) {
            const float e = es[i * TQ + tid];
            if (e > wthr) {
                const float w = __expf(LSCALE * (e - em));
                lsum += w;
                const u64* v2 =
                    (const u64*)(vb + (long)(ckq[tid * NCAND + i] & KEYMASK) * HDIM);
                const u64 w2 = pack2(w, w);
#pragma unroll
                for (int j = 0; j < HDIM / 2; j++) o2[j] = ffma2(w2, v2[j], o2[j]);
            }
        }
        const float inv = 1.0f / lsum;
        const u64 inv2 = pack2(inv, inv);
        u64* og = (u64*)(O + qrow * HDIM);
#pragma unroll
        for (int j = 0; j < HDIM / 2; j++) {
            u64 r;
            asm("mul.rn.f32x2 %0, %1, %2;" : "=l"(r) : "l"(o2[j]), "l"(inv2));
            og[j] = r;
        }
    }
}

extern "C" void kernel_launch(void* const* d_in, const int* in_sizes, int n_in,
                              void* d_out, int out_size) {
    const float* Q = (const float*)d_in[0];
    const float* K = (const float*)d_in[1];
    const float* V = (const float*)d_in[2];
    float* O = (float*)d_out;

    k_convert_kernel<<<N_BH * NKT, 256>>>(K);

    cudaFuncSetAttribute(sdpa_r13_kernel,
                         cudaFuncAttributeMaxDynamicSharedMemorySize, SMEM_BYTES);
    dim3 grid(S_LEN / TQ, N_BH);  // (8, 64)
    dim3 block(THREADS);
    sdpa_r13_kernel<<<grid, block, SMEM_BYTES>>>(Q, K, V, O);
}